// round 1
// baseline (speedup 1.0000x reference)
#include <cuda_runtime.h>
#include <math.h>

// Problem constants
#define S_LEN   2048
#define D_MODEL 1024
#define NHEAD   16
#define HDIM    64
#define BATCH   4
#define BH      (BATCH * NHEAD)   // 64

// Scratch (device globals — no allocation allowed)
__device__ float g_q[(size_t)BH * S_LEN * HDIM];      // [B,H,S,hd] rope'd
__device__ float g_k[(size_t)BH * S_LEN * HDIM];      // [B,H,S,hd] rope'd
__device__ float g_v[(size_t)BH * S_LEN * HDIM];      // [B,H,S,hd]
__device__ float g_attn[(size_t)BATCH * S_LEN * D_MODEL]; // [B,S,D] pre-projection
__device__ float g_cos[S_LEN * (HDIM / 2)];
__device__ float g_sin[S_LEN * (HDIM / 2)];

// ---------------------------------------------------------------------------
// RoPE table: inv_freq = 10000^(-2i/64); ang = pos * inv_freq (all fp32, as ref)
// ---------------------------------------------------------------------------
__global__ void rope_table_kernel() {
    int idx = blockIdx.x * blockDim.x + threadIdx.x;
    if (idx >= S_LEN * (HDIM / 2)) return;
    int s = idx >> 5;          // position
    int i = idx & 31;          // pair index
    // log2(10000) = 13.287712379549449
    float inv = exp2f(-13.287712379549449f * (2.0f * (float)i / 64.0f));
    float ang = (float)s * inv;
    float sn, cs;
    sincosf(ang, &sn, &cs);
    g_cos[idx] = cs;
    g_sin[idx] = sn;
}

#define FMA16(ACC, A, B)                                                     \
    ACC[0][0] += A.x * B.x; ACC[0][1] += A.x * B.y;                          \
    ACC[0][2] += A.x * B.z; ACC[0][3] += A.x * B.w;                          \
    ACC[1][0] += A.y * B.x; ACC[1][1] += A.y * B.y;                          \
    ACC[1][2] += A.y * B.z; ACC[1][3] += A.y * B.w;                          \
    ACC[2][0] += A.z * B.x; ACC[2][1] += A.z * B.y;                          \
    ACC[2][2] += A.z * B.z; ACC[2][3] += A.z * B.w;                          \
    ACC[3][0] += A.w * B.x; ACC[3][1] += A.w * B.y;                          \
    ACC[3][2] += A.w * B.z; ACC[3][3] += A.w * B.w;

// ---------------------------------------------------------------------------
// QKV projection: qkv[m,n] = sum_k x[m,k] * w_qkv[n,k]
// M=8192, N=3072, K=1024.  Epilogue: RoPE (q,k) + scatter to [B,H,S,hd].
// Block tile 64x64, BK=16, 256 threads, 4x4 micro-tile.
// Smem stored K-outer transposed: As[k][m], pad 68 for aligned float4 reads.
// ---------------------------------------------------------------------------
__global__ __launch_bounds__(256) void qkv_rope_gemm(
    const float* __restrict__ X, const float* __restrict__ W)
{
    __shared__ float As[16][68];
    __shared__ float Bs[16][68];
    const int tid = threadIdx.x;
    const int tx = tid & 15, ty = tid >> 4;
    const int m_base = blockIdx.y * 64;
    const int n_base = blockIdx.x * 64;
    const int lk = tid & 15;   // k within BK
    const int lr = tid >> 4;   // row 0..15 (stride 16)
    const float* Xp = X + (size_t)(m_base + lr) * D_MODEL + lk;
    const float* Wp = W + (size_t)(n_base + lr) * D_MODEL + lk;

    float acc[4][4];
#pragma unroll
    for (int i = 0; i < 4; i++)
#pragma unroll
        for (int j = 0; j < 4; j++) acc[i][j] = 0.0f;

    for (int kt = 0; kt < D_MODEL / 16; ++kt) {
#pragma unroll
        for (int r = 0; r < 4; ++r) {
            As[lk][lr + 16 * r] = Xp[(size_t)(16 * r) * D_MODEL + kt * 16];
            Bs[lk][lr + 16 * r] = Wp[(size_t)(16 * r) * D_MODEL + kt * 16];
        }
        __syncthreads();
#pragma unroll
        for (int kk = 0; kk < 16; ++kk) {
            float4 a = *(const float4*)&As[kk][ty * 4];
            float4 b = *(const float4*)&Bs[kk][tx * 4];
            FMA16(acc, a, b)
        }
        __syncthreads();
    }

    // Epilogue: 4 consecutive n columns, all within one head (64-aligned tiles)
    const int n0 = n_base + tx * 4;
    const int part = n0 >> 10;          // 0=q, 1=k, 2=v
    const int c = n0 & 1023;
    const int h = c >> 6;
    const int d0 = c & 63;
    float* dst = (part == 0) ? g_q : (part == 1) ? g_k : g_v;

#pragma unroll
    for (int i = 0; i < 4; ++i) {
        int m = m_base + ty * 4 + i;
        int b = m >> 11;
        int s = m & 2047;
        float v0 = acc[i][0], v1 = acc[i][1], v2 = acc[i][2], v3 = acc[i][3];
        if (part < 2) {
            int i0 = d0 >> 1;   // rope pair index of (d0, d0+1)
            float c0 = g_cos[s * 32 + i0],     s0 = g_sin[s * 32 + i0];
            float c1 = g_cos[s * 32 + i0 + 1], s1 = g_sin[s * 32 + i0 + 1];
            float r0 = v0 * c0 - v1 * s0;
            float r1 = v0 * s0 + v1 * c0;
            float r2 = v2 * c1 - v3 * s1;
            float r3 = v2 * s1 + v3 * c1;
            v0 = r0; v1 = r1; v2 = r2; v3 = r3;
        }
        *(float4*)(dst + (((size_t)(b * NHEAD + h) * S_LEN + s) * HDIM + d0)) =
            make_float4(v0, v1, v2, v3);
    }
}

// ---------------------------------------------------------------------------
// Flash attention (fp32, causal + key padding). One CTA per (bh, 64-query tile).
// 256 threads, 4x4 micro-tiles for both S=QK^T and O+=P*V.
// Smem: Qt[d][q], Kt[d][k] (transposed, pad 68), Pt[k][q] (pad 68), Vs[k][d].
// ---------------------------------------------------------------------------
#define ATTN_SMEM_FLOATS (3 * 64 * 68 + 64 * 64)
#define ATTN_SMEM_BYTES  (ATTN_SMEM_FLOATS * 4 + 64 * 4)

__global__ __launch_bounds__(256) void attn_kernel(const int* __restrict__ pmask)
{
    extern __shared__ float sm[];
    float* Qt = sm;                   // [64][68]
    float* Kt = Qt + 64 * 68;         // [64][68]
    float* Pt = Kt + 64 * 68;         // [64][68]
    float* Vs = Pt + 64 * 68;         // [64][64]
    int*   pm = (int*)(Vs + 64 * 64); // [64]

    const int qt = (int)gridDim.x - 1 - (int)blockIdx.x; // heavy tiles first
    const int bh = blockIdx.y;
    const int b = bh >> 4;
    const int h = bh & 15;
    const int tid = threadIdx.x;
    const int tx = tid & 15, ty = tid >> 4;
    const int qbase = qt * 64;
    const float scale = 0.125f;  // 1/sqrt(64)

    // Load Q tile transposed
    const float* Qg = g_q + ((size_t)bh * S_LEN + qbase) * HDIM;
    for (int e = tid; e < 4096; e += 256) {
        int r = e >> 6, d = e & 63;
        Qt[d * 68 + r] = Qg[r * 64 + d];
    }

    float m_i[4], l_i[4], O[4][4];
#pragma unroll
    for (int i = 0; i < 4; i++) {
        m_i[i] = -INFINITY; l_i[i] = 0.0f;
#pragma unroll
        for (int j = 0; j < 4; j++) O[i][j] = 0.0f;
    }

    for (int kt = 0; kt <= qt; ++kt) {
        const int kbase = kt * 64;
        __syncthreads();  // protect prior-iter smem reads before overwrite
        const float*  Kg = g_k + ((size_t)bh * S_LEN + kbase) * HDIM;
        const float4* Vg = (const float4*)(g_v + ((size_t)bh * S_LEN + kbase) * HDIM);
        for (int e = tid; e < 4096; e += 256) {
            int r = e >> 6, d = e & 63;
            Kt[d * 68 + r] = Kg[r * 64 + d];
        }
        for (int f = tid; f < 1024; f += 256)
            ((float4*)Vs)[f] = Vg[f];
        if (tid < 64) pm[tid] = pmask[b * S_LEN + kbase + tid];
        __syncthreads();

        // S = Q K^T
        float p[4][4];
#pragma unroll
        for (int i = 0; i < 4; i++)
#pragma unroll
            for (int j = 0; j < 4; j++) p[i][j] = 0.0f;

#pragma unroll 8
        for (int d = 0; d < 64; ++d) {
            float4 qv = *(const float4*)&Qt[d * 68 + ty * 4];
            float4 kv = *(const float4*)&Kt[d * 68 + tx * 4];
            FMA16(p, qv, kv)
        }

        // scale + causal / padding mask
#pragma unroll
        for (int i = 0; i < 4; i++) {
            int qi = qbase + ty * 4 + i;
#pragma unroll
            for (int j = 0; j < 4; j++) {
                int kj = kbase + tx * 4 + j;
                float v = p[i][j] * scale;
                if (kj > qi || pm[tx * 4 + j] == 0) v = -1e30f;
                p[i][j] = v;
            }
        }

        // online softmax (row state replicated across the 16 tx threads)
#pragma unroll
        for (int i = 0; i < 4; i++) {
            float v = fmaxf(fmaxf(p[i][0], p[i][1]), fmaxf(p[i][2], p[i][3]));
            v = fmaxf(v, __shfl_xor_sync(0xffffffffu, v, 1));
            v = fmaxf(v, __shfl_xor_sync(0xffffffffu, v, 2));
            v = fmaxf(v, __shfl_xor_sync(0xffffffffu, v, 4));
            v = fmaxf(v, __shfl_xor_sync(0xffffffffu, v, 8));
            float mn = fmaxf(m_i[i], v);
            float al = __expf(m_i[i] - mn);
            float rs = 0.0f;
#pragma unroll
            for (int j = 0; j < 4; j++) {
                p[i][j] = __expf(p[i][j] - mn);
                rs += p[i][j];
            }
            rs += __shfl_xor_sync(0xffffffffu, rs, 1);
            rs += __shfl_xor_sync(0xffffffffu, rs, 2);
            rs += __shfl_xor_sync(0xffffffffu, rs, 4);
            rs += __shfl_xor_sync(0xffffffffu, rs, 8);
            l_i[i] = l_i[i] * al + rs;
            m_i[i] = mn;
#pragma unroll
            for (int j = 0; j < 4; j++) O[i][j] *= al;
        }

        // stage P transposed for the PV GEMM
#pragma unroll
        for (int i = 0; i < 4; i++)
#pragma unroll
            for (int j = 0; j < 4; j++)
                Pt[(tx * 4 + j) * 68 + ty * 4 + i] = p[i][j];
        __syncthreads();

        // O += P * V
#pragma unroll 8
        for (int j2 = 0; j2 < 64; ++j2) {
            float4 pv = *(const float4*)&Pt[j2 * 68 + ty * 4];
            float4 vv = *(const float4*)&Vs[j2 * 64 + tx * 4];
            FMA16(O, pv, vv)
        }
    }

    // normalize + write [B,S,D] (heads concatenated)
#pragma unroll
    for (int i = 0; i < 4; i++) {
        float inv = 1.0f / l_i[i];
        int qi = qbase + ty * 4 + i;
        float4 o = make_float4(O[i][0] * inv, O[i][1] * inv,
                               O[i][2] * inv, O[i][3] * inv);
        *(float4*)(g_attn + ((size_t)b * S_LEN + qi) * D_MODEL + h * HDIM + tx * 4) = o;
    }
}

// ---------------------------------------------------------------------------
// Output projection: out[m,n] = sum_k attn[m,k] * w_o[n,k]
// M=8192, N=1024, K=1024.
// ---------------------------------------------------------------------------
__global__ __launch_bounds__(256) void out_gemm(
    const float* __restrict__ W, float* __restrict__ Out)
{
    __shared__ float As[16][68];
    __shared__ float Bs[16][68];
    const int tid = threadIdx.x;
    const int tx = tid & 15, ty = tid >> 4;
    const int m_base = blockIdx.y * 64;
    const int n_base = blockIdx.x * 64;
    const int lk = tid & 15;
    const int lr = tid >> 4;
    const float* Ap = g_attn + (size_t)(m_base + lr) * D_MODEL + lk;
    const float* Wp = W + (size_t)(n_base + lr) * D_MODEL + lk;

    float acc[4][4];
#pragma unroll
    for (int i = 0; i < 4; i++)
#pragma unroll
        for (int j = 0; j < 4; j++) acc[i][j] = 0.0f;

    for (int kt = 0; kt < D_MODEL / 16; ++kt) {
#pragma unroll
        for (int r = 0; r < 4; ++r) {
            As[lk][lr + 16 * r] = Ap[(size_t)(16 * r) * D_MODEL + kt * 16];
            Bs[lk][lr + 16 * r] = Wp[(size_t)(16 * r) * D_MODEL + kt * 16];
        }
        __syncthreads();
#pragma unroll
        for (int kk = 0; kk < 16; ++kk) {
            float4 a = *(const float4*)&As[kk][ty * 4];
            float4 b = *(const float4*)&Bs[kk][tx * 4];
            FMA16(acc, a, b)
        }
        __syncthreads();
    }

#pragma unroll
    for (int i = 0; i < 4; ++i) {
        int m = m_base + ty * 4 + i;
        *(float4*)(Out + (size_t)m * D_MODEL + n_base + tx * 4) =
            make_float4(acc[i][0], acc[i][1], acc[i][2], acc[i][3]);
    }
}

// ---------------------------------------------------------------------------
extern "C" void kernel_launch(void* const* d_in, const int* in_sizes, int n_in,
                              void* d_out, int out_size)
{
    const float* x      = (const float*)d_in[0];
    const int*   pmask  = (const int*)d_in[1];
    const float* w_qkv  = (const float*)d_in[2];
    const float* w_o    = (const float*)d_in[3];
    float*       out    = (float*)d_out;

    cudaFuncSetAttribute(attn_kernel,
                         cudaFuncAttributeMaxDynamicSharedMemorySize,
                         ATTN_SMEM_BYTES);

    rope_table_kernel<<<(S_LEN * 32 + 255) / 256, 256>>>();
    qkv_rope_gemm<<<dim3(3 * D_MODEL / 64, (BATCH * S_LEN) / 64), 256>>>(x, w_qkv);
    attn_kernel<<<dim3(S_LEN / 64, BH), 256, ATTN_SMEM_BYTES>>>(pmask);
    out_gemm<<<dim3(D_MODEL / 64, (BATCH * S_LEN) / 64), 256>>>(w_o, out);
}

// round 2
// speedup vs baseline: 1.6208x; 1.6208x over previous
#include <cuda_runtime.h>
#include <math.h>
#include <stdint.h>

// Problem constants
#define S_LEN   2048
#define D_MODEL 1024
#define NHEAD   16
#define HDIM    64
#define BATCH   4
#define BH      (BATCH * NHEAD)   // 64

// Scratch (device globals — no allocation allowed)
__device__ float g_q[(size_t)BH * S_LEN * HDIM];      // [B,H,S,hd] rope'd
__device__ float g_k[(size_t)BH * S_LEN * HDIM];      // [B,H,S,hd] rope'd
__device__ float g_v[(size_t)BH * S_LEN * HDIM];      // [B,H,S,hd]
__device__ float g_attn[(size_t)BATCH * S_LEN * D_MODEL]; // [B,S,D] pre-projection
__device__ float g_cos[S_LEN * (HDIM / 2)];
__device__ float g_sin[S_LEN * (HDIM / 2)];

// ---------------------------------------------------------------------------
// RoPE table
// ---------------------------------------------------------------------------
__global__ void rope_table_kernel() {
    int idx = blockIdx.x * blockDim.x + threadIdx.x;
    if (idx >= S_LEN * (HDIM / 2)) return;
    int s = idx >> 5;
    int i = idx & 31;
    float inv = exp2f(-13.287712379549449f * (2.0f * (float)i / 64.0f));
    float ang = (float)s * inv;
    float sn, cs;
    sincosf(ang, &sn, &cs);
    g_cos[idx] = cs;
    g_sin[idx] = sn;
}

// ---------------------------------------------------------------------------
// tf32 helpers
// ---------------------------------------------------------------------------
__device__ __forceinline__ float to_tf32(float x) {
    float r;
    asm("cvt.rna.tf32.f32 %0, %1;" : "=f"(r) : "f"(x));
    return r;
}

__device__ __forceinline__ void mma_m16n8k8(
    float* c, float a0, float a1, float a2, float a3, float b0, float b1)
{
    uint32_t ua0 = __float_as_uint(a0), ua1 = __float_as_uint(a1);
    uint32_t ua2 = __float_as_uint(a2), ua3 = __float_as_uint(a3);
    uint32_t ub0 = __float_as_uint(b0), ub1 = __float_as_uint(b1);
    asm volatile(
        "mma.sync.aligned.m16n8k8.row.col.f32.tf32.tf32.f32 "
        "{%0,%1,%2,%3}, {%4,%5,%6,%7}, {%8,%9}, {%0,%1,%2,%3};"
        : "+f"(c[0]), "+f"(c[1]), "+f"(c[2]), "+f"(c[3])
        : "r"(ua0), "r"(ua1), "r"(ua2), "r"(ua3), "r"(ub0), "r"(ub1));
}

__device__ __forceinline__ void st_tf32_4(float* p, float4 v) {
    p[0] = to_tf32(v.x); p[1] = to_tf32(v.y);
    p[2] = to_tf32(v.z); p[3] = to_tf32(v.w);
}

// ---------------------------------------------------------------------------
// tf32 tensor-core GEMM: C[m,n] = sum_k A[m,k] * Bw[n,k]   (K = 1024)
// BM=128, BN=128, BK=16. 256 threads, warp grid 2(m)x4(n), warp tile 64x32.
// Fragment k-permutation (pos r <-> k 2r, pos r+4 <-> k 2r+1) applied to BOTH
// A and B so every fragment load is one aligned float2 LDS.
// MODE 0: qkv projection -> RoPE + head-scatter to g_q/g_k/g_v
// MODE 1: plain store to Out (output projection)
// ---------------------------------------------------------------------------
template<int MODE>
__global__ __launch_bounds__(256, 2) void mm_tf32(
    const float* __restrict__ A, const float* __restrict__ Bw,
    float* __restrict__ Out)
{
    __shared__ float As[128][20];
    __shared__ float Bs[128][20];

    const int tid    = threadIdx.x;
    const int m_base = blockIdx.y * 128;
    const int n_base = blockIdx.x * 128;

    // global staging: each thread loads 2 float4 from A and 2 from B per tile
    const int ldr = tid >> 2;          // 0..63
    const int ldc = (tid & 3) * 4;     // 0,4,8,12
    const float* Ag = A  + (size_t)(m_base + ldr) * 1024 + ldc;
    const float* Bg = Bw + (size_t)(n_base + ldr) * 1024 + ldc;

    const int warp = tid >> 5;
    const int lane = tid & 31;
    const int wm = warp & 1;           // m-warp (0..1) -> rows wm*64
    const int wn = warp >> 1;          // n-warp (0..3) -> cols wn*32
    const int g  = lane >> 2;          // groupID 0..7
    const int tg = lane & 3;           // thread in group

    float acc[4][4][4];
#pragma unroll
    for (int mi = 0; mi < 4; mi++)
#pragma unroll
        for (int ni = 0; ni < 4; ni++)
#pragma unroll
            for (int j = 0; j < 4; j++) acc[mi][ni][j] = 0.0f;

    // stage tile 0
    {
        st_tf32_4(&As[ldr][ldc],      *(const float4*)(Ag));
        st_tf32_4(&As[ldr + 64][ldc], *(const float4*)(Ag + (size_t)64 * 1024));
        st_tf32_4(&Bs[ldr][ldc],      *(const float4*)(Bg));
        st_tf32_4(&Bs[ldr + 64][ldc], *(const float4*)(Bg + (size_t)64 * 1024));
    }
    __syncthreads();

    for (int kt = 0; kt < 64; ++kt) {
        float4 pa0, pa1, pb0, pb1;
        if (kt < 63) {
            const float* Ap = Ag + (kt + 1) * 16;
            const float* Bp = Bg + (kt + 1) * 16;
            pa0 = *(const float4*)(Ap);
            pa1 = *(const float4*)(Ap + (size_t)64 * 1024);
            pb0 = *(const float4*)(Bp);
            pb1 = *(const float4*)(Bp + (size_t)64 * 1024);
        }

#pragma unroll
        for (int ks = 0; ks < 2; ++ks) {
            const int k0 = ks * 8 + 2 * tg;
            float2 af[4][2], bf[4];
#pragma unroll
            for (int mi = 0; mi < 4; mi++) {
                int r = wm * 64 + mi * 16 + g;
                af[mi][0] = *(const float2*)&As[r][k0];       // a0 (.x), a2 (.y)
                af[mi][1] = *(const float2*)&As[r + 8][k0];   // a1 (.x), a3 (.y)
            }
#pragma unroll
            for (int ni = 0; ni < 4; ni++) {
                int cN = wn * 32 + ni * 8 + g;
                bf[ni] = *(const float2*)&Bs[cN][k0];          // b0 (.x), b1 (.y)
            }
#pragma unroll
            for (int mi = 0; mi < 4; mi++)
#pragma unroll
                for (int ni = 0; ni < 4; ni++)
                    mma_m16n8k8(acc[mi][ni],
                                af[mi][0].x, af[mi][1].x,
                                af[mi][0].y, af[mi][1].y,
                                bf[ni].x, bf[ni].y);
        }

        if (kt < 63) {
            __syncthreads();
            st_tf32_4(&As[ldr][ldc],      pa0);
            st_tf32_4(&As[ldr + 64][ldc], pa1);
            st_tf32_4(&Bs[ldr][ldc],      pb0);
            st_tf32_4(&Bs[ldr + 64][ldc], pb1);
            __syncthreads();
        }
    }

    // epilogue
#pragma unroll
    for (int mi = 0; mi < 4; mi++) {
        int row0 = m_base + wm * 64 + mi * 16 + g;
#pragma unroll
        for (int ni = 0; ni < 4; ni++) {
            int coln = n_base + wn * 32 + ni * 8 + 2 * tg;   // even
            if (MODE == 0) {
                int part = coln >> 10;          // 0=q, 1=k, 2=v
                int cc   = coln & 1023;
                int h    = cc >> 6;
                int d0   = cc & 63;
                int i0   = d0 >> 1;
                float* dst = (part == 0) ? g_q : (part == 1) ? g_k : g_v;
#pragma unroll
                for (int half = 0; half < 2; half++) {
                    int m = row0 + half * 8;
                    int b = m >> 11, s = m & 2047;
                    float v0 = acc[mi][ni][half * 2 + 0];
                    float v1 = acc[mi][ni][half * 2 + 1];
                    if (part < 2) {
                        float cs = g_cos[s * 32 + i0], sn = g_sin[s * 32 + i0];
                        float r0 = v0 * cs - v1 * sn;
                        float r1 = v0 * sn + v1 * cs;
                        v0 = r0; v1 = r1;
                    }
                    *(float2*)(dst + (((size_t)(b * NHEAD + h) * S_LEN + s) * HDIM + d0))
                        = make_float2(v0, v1);
                }
            } else {
#pragma unroll
                for (int half = 0; half < 2; half++) {
                    int m = row0 + half * 8;
                    *(float2*)(Out + (size_t)m * 1024 + coln)
                        = make_float2(acc[mi][ni][half * 2 + 0],
                                      acc[mi][ni][half * 2 + 1]);
                }
            }
        }
    }
}

// ---------------------------------------------------------------------------
// Flash attention (fp32, causal + key padding) — unchanged from round 1.
// ---------------------------------------------------------------------------
#define FMA16(ACC, A, B)                                                     \
    ACC[0][0] += A.x * B.x; ACC[0][1] += A.x * B.y;                          \
    ACC[0][2] += A.x * B.z; ACC[0][3] += A.x * B.w;                          \
    ACC[1][0] += A.y * B.x; ACC[1][1] += A.y * B.y;                          \
    ACC[1][2] += A.y * B.z; ACC[1][3] += A.y * B.w;                          \
    ACC[2][0] += A.z * B.x; ACC[2][1] += A.z * B.y;                          \
    ACC[2][2] += A.z * B.z; ACC[2][3] += A.z * B.w;                          \
    ACC[3][0] += A.w * B.x; ACC[3][1] += A.w * B.y;                          \
    ACC[3][2] += A.w * B.z; ACC[3][3] += A.w * B.w;

#define ATTN_SMEM_FLOATS (3 * 64 * 68 + 64 * 64)
#define ATTN_SMEM_BYTES  (ATTN_SMEM_FLOATS * 4 + 64 * 4)

__global__ __launch_bounds__(256) void attn_kernel(const int* __restrict__ pmask)
{
    extern __shared__ float sm[];
    float* Qt = sm;                   // [64][68]
    float* Kt = Qt + 64 * 68;         // [64][68]
    float* Pt = Kt + 64 * 68;         // [64][68]
    float* Vs = Pt + 64 * 68;         // [64][64]
    int*   pm = (int*)(Vs + 64 * 64); // [64]

    const int qt = (int)gridDim.x - 1 - (int)blockIdx.x; // heavy tiles first
    const int bh = blockIdx.y;
    const int b = bh >> 4;
    const int h = bh & 15;
    const int tid = threadIdx.x;
    const int tx = tid & 15, ty = tid >> 4;
    const int qbase = qt * 64;
    const float scale = 0.125f;

    const float* Qg = g_q + ((size_t)bh * S_LEN + qbase) * HDIM;
    for (int e = tid; e < 4096; e += 256) {
        int r = e >> 6, d = e & 63;
        Qt[d * 68 + r] = Qg[r * 64 + d];
    }

    float m_i[4], l_i[4], O[4][4];
#pragma unroll
    for (int i = 0; i < 4; i++) {
        m_i[i] = -INFINITY; l_i[i] = 0.0f;
#pragma unroll
        for (int j = 0; j < 4; j++) O[i][j] = 0.0f;
    }

    for (int kt = 0; kt <= qt; ++kt) {
        const int kbase = kt * 64;
        __syncthreads();
        const float*  Kg = g_k + ((size_t)bh * S_LEN + kbase) * HDIM;
        const float4* Vg = (const float4*)(g_v + ((size_t)bh * S_LEN + kbase) * HDIM);
        for (int e = tid; e < 4096; e += 256) {
            int r = e >> 6, d = e & 63;
            Kt[d * 68 + r] = Kg[r * 64 + d];
        }
        for (int f = tid; f < 1024; f += 256)
            ((float4*)Vs)[f] = Vg[f];
        if (tid < 64) pm[tid] = pmask[b * S_LEN + kbase + tid];
        __syncthreads();

        float p[4][4];
#pragma unroll
        for (int i = 0; i < 4; i++)
#pragma unroll
            for (int j = 0; j < 4; j++) p[i][j] = 0.0f;

#pragma unroll 8
        for (int d = 0; d < 64; ++d) {
            float4 qv = *(const float4*)&Qt[d * 68 + ty * 4];
            float4 kv = *(const float4*)&Kt[d * 68 + tx * 4];
            FMA16(p, qv, kv)
        }

#pragma unroll
        for (int i = 0; i < 4; i++) {
            int qi = qbase + ty * 4 + i;
#pragma unroll
            for (int j = 0; j < 4; j++) {
                int kj = kbase + tx * 4 + j;
                float v = p[i][j] * scale;
                if (kj > qi || pm[tx * 4 + j] == 0) v = -1e30f;
                p[i][j] = v;
            }
        }

#pragma unroll
        for (int i = 0; i < 4; i++) {
            float v = fmaxf(fmaxf(p[i][0], p[i][1]), fmaxf(p[i][2], p[i][3]));
            v = fmaxf(v, __shfl_xor_sync(0xffffffffu, v, 1));
            v = fmaxf(v, __shfl_xor_sync(0xffffffffu, v, 2));
            v = fmaxf(v, __shfl_xor_sync(0xffffffffu, v, 4));
            v = fmaxf(v, __shfl_xor_sync(0xffffffffu, v, 8));
            float mn = fmaxf(m_i[i], v);
            float al = __expf(m_i[i] - mn);
            float rs = 0.0f;
#pragma unroll
            for (int j = 0; j < 4; j++) {
                p[i][j] = __expf(p[i][j] - mn);
                rs += p[i][j];
            }
            rs += __shfl_xor_sync(0xffffffffu, rs, 1);
            rs += __shfl_xor_sync(0xffffffffu, rs, 2);
            rs += __shfl_xor_sync(0xffffffffu, rs, 4);
            rs += __shfl_xor_sync(0xffffffffu, rs, 8);
            l_i[i] = l_i[i] * al + rs;
            m_i[i] = mn;
#pragma unroll
            for (int j = 0; j < 4; j++) O[i][j] *= al;
        }

#pragma unroll
        for (int i = 0; i < 4; i++)
#pragma unroll
            for (int j = 0; j < 4; j++)
                Pt[(tx * 4 + j) * 68 + ty * 4 + i] = p[i][j];
        __syncthreads();

#pragma unroll 8
        for (int j2 = 0; j2 < 64; ++j2) {
            float4 pv = *(const float4*)&Pt[j2 * 68 + ty * 4];
            float4 vv = *(const float4*)&Vs[j2 * 64 + tx * 4];
            FMA16(O, pv, vv)
        }
    }

#pragma unroll
    for (int i = 0; i < 4; i++) {
        float inv = 1.0f / l_i[i];
        int qi = qbase + ty * 4 + i;
        float4 o = make_float4(O[i][0] * inv, O[i][1] * inv,
                               O[i][2] * inv, O[i][3] * inv);
        *(float4*)(g_attn + ((size_t)b * S_LEN + qi) * D_MODEL + h * HDIM + tx * 4) = o;
    }
}

// ---------------------------------------------------------------------------
extern "C" void kernel_launch(void* const* d_in, const int* in_sizes, int n_in,
                              void* d_out, int out_size)
{
    const float* x      = (const float*)d_in[0];
    const int*   pmask  = (const int*)d_in[1];
    const float* w_qkv  = (const float*)d_in[2];
    const float* w_o    = (const float*)d_in[3];
    float*       out    = (float*)d_out;

    cudaFuncSetAttribute(attn_kernel,
                         cudaFuncAttributeMaxDynamicSharedMemorySize,
                         ATTN_SMEM_BYTES);

    float* attn_ptr = nullptr;
    cudaGetSymbolAddress((void**)&attn_ptr, g_attn);

    rope_table_kernel<<<(S_LEN * 32 + 255) / 256, 256>>>();
    // QKV projection + RoPE: M=8192, N=3072
    mm_tf32<0><<<dim3(3 * D_MODEL / 128, (BATCH * S_LEN) / 128), 256>>>(x, w_qkv, nullptr);
    attn_kernel<<<dim3(S_LEN / 64, BH), 256, ATTN_SMEM_BYTES>>>(pmask);
    // Output projection: M=8192, N=1024
    mm_tf32<1><<<dim3(D_MODEL / 128, (BATCH * S_LEN) / 128), 256>>>(attn_ptr, w_o, out);
}

// round 4
// speedup vs baseline: 2.8753x; 1.7740x over previous
#include <cuda_runtime.h>
#include <math.h>
#include <stdint.h>

// Problem constants
#define S_LEN   2048
#define D_MODEL 1024
#define NHEAD   16
#define HDIM    64
#define BATCH   4
#define BH      (BATCH * NHEAD)   // 64

// Scratch (device globals — no allocation allowed)
__device__ float g_q[(size_t)BH * S_LEN * HDIM];          // [B,H,S,hd] rope'd, tf32-rounded
__device__ float g_k[(size_t)BH * S_LEN * HDIM];
__device__ float g_v[(size_t)BH * S_LEN * HDIM];
__device__ float g_attn[(size_t)BATCH * S_LEN * D_MODEL]; // [B,S,D], tf32-rounded
__device__ float g_cos[S_LEN * (HDIM / 2)];
__device__ float g_sin[S_LEN * (HDIM / 2)];
__device__ float g_xc[(size_t)BATCH * S_LEN * D_MODEL];   // tf32-rounded x
__device__ float g_wc[(size_t)3 * D_MODEL * D_MODEL];     // tf32-rounded w_qkv
__device__ float g_woc[(size_t)D_MODEL * D_MODEL];        // tf32-rounded w_o
__device__ float g_bias[BATCH * S_LEN];                   // 0 or -1e30 padding bias

// ---------------------------------------------------------------------------
// helpers
// ---------------------------------------------------------------------------
__device__ __forceinline__ float to_tf32(float x) {
    float r;
    asm("cvt.rna.tf32.f32 %0, %1;" : "=f"(r) : "f"(x));
    return r;
}

__device__ __forceinline__ void mma_m16n8k8(
    float* c, float a0, float a1, float a2, float a3, float b0, float b1)
{
    uint32_t ua0 = __float_as_uint(a0), ua1 = __float_as_uint(a1);
    uint32_t ua2 = __float_as_uint(a2), ua3 = __float_as_uint(a3);
    uint32_t ub0 = __float_as_uint(b0), ub1 = __float_as_uint(b1);
    asm volatile(
        "mma.sync.aligned.m16n8k8.row.col.f32.tf32.tf32.f32 "
        "{%0,%1,%2,%3}, {%4,%5,%6,%7}, {%8,%9}, {%0,%1,%2,%3};"
        : "+f"(c[0]), "+f"(c[1]), "+f"(c[2]), "+f"(c[3])
        : "r"(ua0), "r"(ua1), "r"(ua2), "r"(ua3), "r"(ub0), "r"(ub1));
}

__device__ __forceinline__ uint32_t smem_u32(const void* p) {
    return (uint32_t)__cvta_generic_to_shared(p);
}
#define CP16(d, s) asm volatile("cp.async.ca.shared.global [%0], [%1], 16;" :: "r"(d), "l"(s))
#define CP_COMMIT  asm volatile("cp.async.commit_group;")
#define CP_WAIT1   asm volatile("cp.async.wait_group 1;")

// ---------------------------------------------------------------------------
// small prep kernels
// ---------------------------------------------------------------------------
__global__ void rope_table_kernel() {
    int idx = blockIdx.x * blockDim.x + threadIdx.x;
    if (idx >= S_LEN * (HDIM / 2)) return;
    int s = idx >> 5;
    int i = idx & 31;
    float inv = exp2f(-13.287712379549449f * (2.0f * (float)i / 64.0f));
    float ang = (float)s * inv;
    float sn, cs;
    sincosf(ang, &sn, &cs);
    g_cos[idx] = cs;
    g_sin[idx] = sn;
}

__global__ void cvt_tf32_kernel(const float4* __restrict__ src,
                                float4* __restrict__ dst, int n4) {
    int i = blockIdx.x * blockDim.x + threadIdx.x;
    if (i >= n4) return;
    float4 v = src[i];
    dst[i] = make_float4(to_tf32(v.x), to_tf32(v.y), to_tf32(v.z), to_tf32(v.w));
}

__global__ void bias_kernel(const int* __restrict__ pmask) {
    int i = blockIdx.x * blockDim.x + threadIdx.x;
    if (i < BATCH * S_LEN)
        g_bias[i] = (pmask[i] == 0) ? -1e30f : 0.0f;
}

// ---------------------------------------------------------------------------
// tf32 tensor-core GEMM: C[m,n] = sum_k A[m,k] * Bw[n,k]   (K = 1024)
// Operands PRE-ROUNDED to tf32 — no cvt in the hot loop.
// MODE 0: qkv projection -> RoPE + head-scatter to g_q/g_k/g_v (tf32-rounded)
// MODE 1: plain fp32 store to Out
// ---------------------------------------------------------------------------
template<int MODE>
__global__ __launch_bounds__(256, 2) void mm_tf32(
    const float* __restrict__ A, const float* __restrict__ Bw,
    float* __restrict__ Out)
{
    __shared__ float As[128][20];
    __shared__ float Bs[128][20];

    const int tid    = threadIdx.x;
    const int m_base = blockIdx.y * 128;
    const int n_base = blockIdx.x * 128;

    const int ldr = tid >> 2;
    const int ldc = (tid & 3) * 4;
    const float* Ag = A  + (size_t)(m_base + ldr) * 1024 + ldc;
    const float* Bg = Bw + (size_t)(n_base + ldr) * 1024 + ldc;

    const int warp = tid >> 5;
    const int lane = tid & 31;
    const int wm = warp & 1;
    const int wn = warp >> 1;
    const int g  = lane >> 2;
    const int tg = lane & 3;

    float acc[4][4][4];
#pragma unroll
    for (int mi = 0; mi < 4; mi++)
#pragma unroll
        for (int ni = 0; ni < 4; ni++)
#pragma unroll
            for (int j = 0; j < 4; j++) acc[mi][ni][j] = 0.0f;

    {
        *(float4*)&As[ldr][ldc]      = *(const float4*)(Ag);
        *(float4*)&As[ldr + 64][ldc] = *(const float4*)(Ag + (size_t)64 * 1024);
        *(float4*)&Bs[ldr][ldc]      = *(const float4*)(Bg);
        *(float4*)&Bs[ldr + 64][ldc] = *(const float4*)(Bg + (size_t)64 * 1024);
    }
    __syncthreads();

    for (int kt = 0; kt < 64; ++kt) {
        float4 pa0, pa1, pb0, pb1;
        if (kt < 63) {
            const float* Ap = Ag + (kt + 1) * 16;
            const float* Bp = Bg + (kt + 1) * 16;
            pa0 = *(const float4*)(Ap);
            pa1 = *(const float4*)(Ap + (size_t)64 * 1024);
            pb0 = *(const float4*)(Bp);
            pb1 = *(const float4*)(Bp + (size_t)64 * 1024);
        }

#pragma unroll
        for (int ks = 0; ks < 2; ++ks) {
            const int k0 = ks * 8 + 2 * tg;
            float2 af[4][2], bf[4];
#pragma unroll
            for (int mi = 0; mi < 4; mi++) {
                int r = wm * 64 + mi * 16 + g;
                af[mi][0] = *(const float2*)&As[r][k0];
                af[mi][1] = *(const float2*)&As[r + 8][k0];
            }
#pragma unroll
            for (int ni = 0; ni < 4; ni++) {
                int cN = wn * 32 + ni * 8 + g;
                bf[ni] = *(const float2*)&Bs[cN][k0];
            }
#pragma unroll
            for (int mi = 0; mi < 4; mi++)
#pragma unroll
                for (int ni = 0; ni < 4; ni++)
                    mma_m16n8k8(acc[mi][ni],
                                af[mi][0].x, af[mi][1].x,
                                af[mi][0].y, af[mi][1].y,
                                bf[ni].x, bf[ni].y);
        }

        if (kt < 63) {
            __syncthreads();
            *(float4*)&As[ldr][ldc]      = pa0;
            *(float4*)&As[ldr + 64][ldc] = pa1;
            *(float4*)&Bs[ldr][ldc]      = pb0;
            *(float4*)&Bs[ldr + 64][ldc] = pb1;
            __syncthreads();
        }
    }

#pragma unroll
    for (int mi = 0; mi < 4; mi++) {
        int row0 = m_base + wm * 64 + mi * 16 + g;
#pragma unroll
        for (int ni = 0; ni < 4; ni++) {
            int coln = n_base + wn * 32 + ni * 8 + 2 * tg;
            if (MODE == 0) {
                int part = coln >> 10;
                int cc   = coln & 1023;
                int h    = cc >> 6;
                int d0   = cc & 63;
                int i0   = d0 >> 1;
                float* dst = (part == 0) ? g_q : (part == 1) ? g_k : g_v;
#pragma unroll
                for (int half = 0; half < 2; half++) {
                    int m = row0 + half * 8;
                    int b = m >> 11, s = m & 2047;
                    float v0 = acc[mi][ni][half * 2 + 0];
                    float v1 = acc[mi][ni][half * 2 + 1];
                    if (part < 2) {
                        float cs = g_cos[s * 32 + i0], sn = g_sin[s * 32 + i0];
                        float r0 = v0 * cs - v1 * sn;
                        float r1 = v0 * sn + v1 * cs;
                        v0 = r0; v1 = r1;
                    }
                    *(float2*)(dst + (((size_t)(b * NHEAD + h) * S_LEN + s) * HDIM + d0))
                        = make_float2(to_tf32(v0), to_tf32(v1));
                }
            } else {
#pragma unroll
                for (int half = 0; half < 2; half++) {
                    int m = row0 + half * 8;
                    *(float2*)(Out + (size_t)m * 1024 + coln)
                        = make_float2(acc[mi][ni][half * 2 + 0],
                                      acc[mi][ni][half * 2 + 1]);
                }
            }
        }
    }
}

// ---------------------------------------------------------------------------
// Tensor-core flash attention (tf32 mma.sync).
// CTA: 256 threads = 8 warps; q-tile 256 rows (warp owns 32 rows = 2 m-subtiles);
// k-tile 64 keys; cp.async double-buffered K/V/bias; causal per-warp tile skip.
// Fragment k-permutation applied to both operands of both MMAs -> the S
// accumulator IS the PV A-fragment (P never round-trips through smem).
// ---------------------------------------------------------------------------
#define ATTN_SM_FLOATS (256*72 + 2*64*72 + 2*64*68 + 2*64)
#define ATTN_SM_BYTES  (ATTN_SM_FLOATS * 4)

// Stage one full 64x64 K tile and 64x64 V tile (+64-float bias) via cp.async.
// 1024 float4 chunks per operand => 4 CP16 per thread per operand.
__device__ __forceinline__ void stage_kv(
    float* Kdst, float* Vdst, float* PMdst,
    const float* Kg, const float* Vg, const float* Bsrc, int tid)
{
#pragma unroll
    for (int i = 0; i < 4; ++i) {
        int idx = tid + i * 256;
        int row = idx >> 4;
        int c4  = (idx & 15) * 4;
        CP16(smem_u32(Kdst + row * 72 + c4), Kg + (size_t)row * 64 + c4);
        CP16(smem_u32(Vdst + row * 68 + c4), Vg + (size_t)row * 64 + c4);
    }
    if (tid < 16) CP16(smem_u32(PMdst + tid * 4), Bsrc + tid * 4);
}

__global__ __launch_bounds__(256, 1) void attn_tc()
{
    extern __shared__ float sm[];
    float* Qs = sm;                        // [256][72]
    float* Ks = Qs + 256 * 72;             // [2][64][72]
    float* Vs = Ks + 2 * 64 * 72;          // [2][64][68]
    float* PM = Vs + 2 * 64 * 68;          // [2][64]

    const int qt    = 7 - (int)blockIdx.x;          // heavy tiles first
    const int qbase = qt * 256;
    const int bh = blockIdx.y;
    const int b  = bh >> 4, h = bh & 15;
    const int tid  = threadIdx.x;
    const int warp = tid >> 5, lane = tid & 31;
    const int g = lane >> 2, tg = lane & 3;
    const int nkt = 4 * (qt + 1);

    const float* Kg = g_k + (size_t)bh * S_LEN * HDIM;
    const float* Vg = g_v + (size_t)bh * S_LEN * HDIM;
    const float* Bg = g_bias + b * S_LEN;

    // prefetch k-tile 0
    stage_kv(Ks, Vs, PM, Kg, Vg, Bg, tid);
    CP_COMMIT;

    // stage Q tile [256][64] -> Qs[256][72]
    {
        const float* Qg = g_q + ((size_t)bh * S_LEN + qbase) * HDIM;
#pragma unroll
        for (int r = 0; r < 16; ++r) {
            int idx = tid + r * 256;
            int row = idx >> 4, c4 = (idx & 15) * 4;
            *(float4*)&Qs[row * 72 + c4] = *(const float4*)&Qg[row * 64 + c4];
        }
    }

    float S[2][8][4], O[2][8][4], mrow[2][2], lrow[2][2];
#pragma unroll
    for (int mt = 0; mt < 2; mt++) {
        mrow[mt][0] = mrow[mt][1] = -INFINITY;
        lrow[mt][0] = lrow[mt][1] = 0.0f;
#pragma unroll
        for (int t = 0; t < 8; t++)
#pragma unroll
            for (int j = 0; j < 4; j++) O[mt][t][j] = 0.0f;
    }

    const int wrow0 = qbase + warp * 32;
    const float scale = 0.125f;   // 1/sqrt(64)

    for (int kt = 0; kt < nkt; ++kt) {
        const int buf   = kt & 1;
        const int kbase = kt * 64;

        if (kt + 1 < nkt) {
            int nb  = (kt + 1) & 1;
            int kb2 = (kt + 1) * 64;
            stage_kv(Ks + nb * 4608, Vs + nb * 4352, PM + nb * 64,
                     Kg + (size_t)kb2 * 64, Vg + (size_t)kb2 * 64, Bg + kb2, tid);
        }
        CP_COMMIT;
        CP_WAIT1;
        __syncthreads();

        if (kbase <= wrow0 + 31) {     // per-warp causal tile skip
            const float* Kb  = Ks + buf * 4608;
            const float* Vb  = Vs + buf * 4352;
            const float* PMb = PM + buf * 64;

            // ---- S = Q K^T
#pragma unroll
            for (int mt = 0; mt < 2; mt++)
#pragma unroll
                for (int nt = 0; nt < 8; nt++)
#pragma unroll
                    for (int j = 0; j < 4; j++) S[mt][nt][j] = 0.0f;

#pragma unroll
            for (int ks = 0; ks < 8; ++ks) {
                int kcol = 8 * ks + 2 * tg;
                float2 a00 = *(const float2*)&Qs[(warp * 32 + g     ) * 72 + kcol];
                float2 a01 = *(const float2*)&Qs[(warp * 32 + g +  8) * 72 + kcol];
                float2 a10 = *(const float2*)&Qs[(warp * 32 + g + 16) * 72 + kcol];
                float2 a11 = *(const float2*)&Qs[(warp * 32 + g + 24) * 72 + kcol];
#pragma unroll
                for (int nt = 0; nt < 8; ++nt) {
                    float2 bb = *(const float2*)&Kb[(nt * 8 + g) * 72 + kcol];
                    mma_m16n8k8(S[0][nt], a00.x, a01.x, a00.y, a01.y, bb.x, bb.y);
                    mma_m16n8k8(S[1][nt], a10.x, a11.x, a10.y, a11.y, bb.x, bb.y);
                }
            }

            // ---- mask + online softmax
            float2 pmb[8];
#pragma unroll
            for (int nt = 0; nt < 8; nt++)
                pmb[nt] = *(const float2*)&PMb[nt * 8 + 2 * tg];

            const bool do_causal = (kbase + 63 > wrow0);

#pragma unroll
            for (int mt = 0; mt < 2; mt++) {
                int row_lo = wrow0 + mt * 16 + g;
                int row_hi = row_lo + 8;
                float mx_lo = -INFINITY, mx_hi = -INFINITY;
#pragma unroll
                for (int nt = 0; nt < 8; nt++) {
                    int col0 = kbase + nt * 8 + 2 * tg;
                    float v0 = S[mt][nt][0] * scale + pmb[nt].x;
                    float v1 = S[mt][nt][1] * scale + pmb[nt].y;
                    float v2 = S[mt][nt][2] * scale + pmb[nt].x;
                    float v3 = S[mt][nt][3] * scale + pmb[nt].y;
                    if (do_causal) {
                        if (col0     > row_lo) v0 = -1e30f;
                        if (col0 + 1 > row_lo) v1 = -1e30f;
                        if (col0     > row_hi) v2 = -1e30f;
                        if (col0 + 1 > row_hi) v3 = -1e30f;
                    }
                    S[mt][nt][0] = v0; S[mt][nt][1] = v1;
                    S[mt][nt][2] = v2; S[mt][nt][3] = v3;
                    mx_lo = fmaxf(mx_lo, fmaxf(v0, v1));
                    mx_hi = fmaxf(mx_hi, fmaxf(v2, v3));
                }
                mx_lo = fmaxf(mx_lo, __shfl_xor_sync(0xffffffffu, mx_lo, 1));
                mx_lo = fmaxf(mx_lo, __shfl_xor_sync(0xffffffffu, mx_lo, 2));
                mx_hi = fmaxf(mx_hi, __shfl_xor_sync(0xffffffffu, mx_hi, 1));
                mx_hi = fmaxf(mx_hi, __shfl_xor_sync(0xffffffffu, mx_hi, 2));

                float mn_lo = fmaxf(mrow[mt][0], mx_lo);
                float mn_hi = fmaxf(mrow[mt][1], mx_hi);
                float al_lo = __expf(mrow[mt][0] - mn_lo);
                float al_hi = __expf(mrow[mt][1] - mn_hi);

                float s_lo = 0.0f, s_hi = 0.0f;
#pragma unroll
                for (int nt = 0; nt < 8; nt++) {
                    float p0 = __expf(S[mt][nt][0] - mn_lo);
                    float p1 = __expf(S[mt][nt][1] - mn_lo);
                    float p2 = __expf(S[mt][nt][2] - mn_hi);
                    float p3 = __expf(S[mt][nt][3] - mn_hi);
                    s_lo += p0 + p1;
                    s_hi += p2 + p3;
                    S[mt][nt][0] = to_tf32(p0);
                    S[mt][nt][1] = to_tf32(p1);
                    S[mt][nt][2] = to_tf32(p2);
                    S[mt][nt][3] = to_tf32(p3);
                }
                s_lo += __shfl_xor_sync(0xffffffffu, s_lo, 1);
                s_lo += __shfl_xor_sync(0xffffffffu, s_lo, 2);
                s_hi += __shfl_xor_sync(0xffffffffu, s_hi, 1);
                s_hi += __shfl_xor_sync(0xffffffffu, s_hi, 2);

                lrow[mt][0] = lrow[mt][0] * al_lo + s_lo;
                lrow[mt][1] = lrow[mt][1] * al_hi + s_hi;
                mrow[mt][0] = mn_lo;
                mrow[mt][1] = mn_hi;
#pragma unroll
                for (int hd = 0; hd < 8; hd++) {
                    O[mt][hd][0] *= al_lo;
                    O[mt][hd][1] *= al_lo;
                    O[mt][hd][2] *= al_hi;
                    O[mt][hd][3] *= al_hi;
                }
            }

            // ---- O += P V  (A-fragments = S accumulators, B from Vs)
#pragma unroll
            for (int ks = 0; ks < 8; ++ks) {
#pragma unroll
                for (int hd = 0; hd < 8; ++hd) {
                    float b0 = Vb[(ks * 8 + 2 * tg    ) * 68 + hd * 8 + g];
                    float b1 = Vb[(ks * 8 + 2 * tg + 1) * 68 + hd * 8 + g];
                    mma_m16n8k8(O[0][hd], S[0][ks][0], S[0][ks][2],
                                          S[0][ks][1], S[0][ks][3], b0, b1);
                    mma_m16n8k8(O[1][hd], S[1][ks][0], S[1][ks][2],
                                          S[1][ks][1], S[1][ks][3], b0, b1);
                }
            }
        }
        __syncthreads();
    }

    // epilogue: normalize + write g_attn (tf32-rounded for the out-proj GEMM)
#pragma unroll
    for (int mt = 0; mt < 2; mt++) {
        float inv_lo = 1.0f / lrow[mt][0];
        float inv_hi = 1.0f / lrow[mt][1];
        int row_lo = wrow0 + mt * 16 + g;
#pragma unroll
        for (int hd = 0; hd < 8; hd++) {
            int col = h * 64 + hd * 8 + 2 * tg;
            *(float2*)(g_attn + ((size_t)b * S_LEN + row_lo) * D_MODEL + col) =
                make_float2(to_tf32(O[mt][hd][0] * inv_lo),
                            to_tf32(O[mt][hd][1] * inv_lo));
            *(float2*)(g_attn + ((size_t)b * S_LEN + row_lo + 8) * D_MODEL + col) =
                make_float2(to_tf32(O[mt][hd][2] * inv_hi),
                            to_tf32(O[mt][hd][3] * inv_hi));
        }
    }
}

// ---------------------------------------------------------------------------
extern "C" void kernel_launch(void* const* d_in, const int* in_sizes, int n_in,
                              void* d_out, int out_size)
{
    const float* x      = (const float*)d_in[0];
    const int*   pmask  = (const int*)d_in[1];
    const float* w_qkv  = (const float*)d_in[2];
    const float* w_o    = (const float*)d_in[3];
    float*       out    = (float*)d_out;

    cudaFuncSetAttribute(attn_tc,
                         cudaFuncAttributeMaxDynamicSharedMemorySize,
                         ATTN_SM_BYTES);

    float *xc, *wc, *woc, *attn_ptr;
    cudaGetSymbolAddress((void**)&xc, g_xc);
    cudaGetSymbolAddress((void**)&wc, g_wc);
    cudaGetSymbolAddress((void**)&woc, g_woc);
    cudaGetSymbolAddress((void**)&attn_ptr, g_attn);

    rope_table_kernel<<<(S_LEN * 32 + 255) / 256, 256>>>();
    // preconvert operands to tf32 (removes all cvt from GEMM hot loops)
    cvt_tf32_kernel<<<(2097152 + 255) / 256, 256>>>((const float4*)x, (float4*)xc, 2097152);
    cvt_tf32_kernel<<<(786432 + 255) / 256, 256>>>((const float4*)w_qkv, (float4*)wc, 786432);
    cvt_tf32_kernel<<<(262144 + 255) / 256, 256>>>((const float4*)w_o, (float4*)woc, 262144);
    bias_kernel<<<(BATCH * S_LEN + 255) / 256, 256>>>(pmask);

    // QKV projection + RoPE: M=8192, N=3072
    mm_tf32<0><<<dim3(3 * D_MODEL / 128, (BATCH * S_LEN) / 128), 256>>>(xc, wc, nullptr);
    // Flash attention (tensor cores)
    attn_tc<<<dim3(8, BH), 256, ATTN_SM_BYTES>>>();
    // Output projection: M=8192, N=1024
    mm_tf32<1><<<dim3(D_MODEL / 128, (BATCH * S_LEN) / 128), 256>>>(attn_ptr, woc, out);
}

// round 5
// speedup vs baseline: 3.0185x; 1.0498x over previous
#include <cuda_runtime.h>
#include <math.h>
#include <stdint.h>

// Problem constants
#define S_LEN   2048
#define D_MODEL 1024
#define NHEAD   16
#define HDIM    64
#define BATCH   4
#define BH      (BATCH * NHEAD)   // 64

// Scratch (device globals — no allocation allowed)
__device__ float g_q[(size_t)BH * S_LEN * HDIM];          // [B,H,S,hd] rope'd, tf32-rounded
__device__ float g_k[(size_t)BH * S_LEN * HDIM];
__device__ float g_v[(size_t)BH * S_LEN * HDIM];
__device__ float g_attn[(size_t)BATCH * S_LEN * D_MODEL]; // [B,S,D], tf32-rounded
__device__ float g_cos[S_LEN * (HDIM / 2)];
__device__ float g_sin[S_LEN * (HDIM / 2)];
__device__ float g_xc[(size_t)BATCH * S_LEN * D_MODEL];   // tf32-rounded x
__device__ float g_wc[(size_t)3 * D_MODEL * D_MODEL];     // tf32-rounded w_qkv
__device__ float g_woc[(size_t)D_MODEL * D_MODEL];        // tf32-rounded w_o
__device__ float g_bias[BATCH * S_LEN];                   // 0 or -1e30 padding bias

// ---------------------------------------------------------------------------
// helpers
// ---------------------------------------------------------------------------
__device__ __forceinline__ float to_tf32(float x) {
    float r;
    asm("cvt.rna.tf32.f32 %0, %1;" : "=f"(r) : "f"(x));
    return r;
}

__device__ __forceinline__ void mma_m16n8k8(
    float* c, float a0, float a1, float a2, float a3, float b0, float b1)
{
    uint32_t ua0 = __float_as_uint(a0), ua1 = __float_as_uint(a1);
    uint32_t ua2 = __float_as_uint(a2), ua3 = __float_as_uint(a3);
    uint32_t ub0 = __float_as_uint(b0), ub1 = __float_as_uint(b1);
    asm volatile(
        "mma.sync.aligned.m16n8k8.row.col.f32.tf32.tf32.f32 "
        "{%0,%1,%2,%3}, {%4,%5,%6,%7}, {%8,%9}, {%0,%1,%2,%3};"
        : "+f"(c[0]), "+f"(c[1]), "+f"(c[2]), "+f"(c[3])
        : "r"(ua0), "r"(ua1), "r"(ua2), "r"(ua3), "r"(ub0), "r"(ub1));
}

__device__ __forceinline__ uint32_t smem_u32(const void* p) {
    return (uint32_t)__cvta_generic_to_shared(p);
}
#define CP16(d, s) asm volatile("cp.async.ca.shared.global [%0], [%1], 16;" :: "r"(d), "l"(s))
#define CP_COMMIT  asm volatile("cp.async.commit_group;")
#define CP_WAIT1   asm volatile("cp.async.wait_group 1;")

// ---------------------------------------------------------------------------
// small prep kernels
// ---------------------------------------------------------------------------
__global__ void rope_table_kernel() {
    int idx = blockIdx.x * blockDim.x + threadIdx.x;
    if (idx >= S_LEN * (HDIM / 2)) return;
    int s = idx >> 5;
    int i = idx & 31;
    float inv = exp2f(-13.287712379549449f * (2.0f * (float)i / 64.0f));
    float ang = (float)s * inv;
    float sn, cs;
    sincosf(ang, &sn, &cs);
    g_cos[idx] = cs;
    g_sin[idx] = sn;
}

__global__ void cvt_tf32_kernel(const float4* __restrict__ src,
                                float4* __restrict__ dst, int n4) {
    int i = blockIdx.x * blockDim.x + threadIdx.x;
    if (i >= n4) return;
    float4 v = src[i];
    dst[i] = make_float4(to_tf32(v.x), to_tf32(v.y), to_tf32(v.z), to_tf32(v.w));
}

__global__ void bias_kernel(const int* __restrict__ pmask) {
    int i = blockIdx.x * blockDim.x + threadIdx.x;
    if (i < BATCH * S_LEN)
        g_bias[i] = (pmask[i] == 0) ? -1e30f : 0.0f;
}

// ---------------------------------------------------------------------------
// tf32 tensor-core GEMM: C[m,n] = sum_k A[m,k] * Bw[n,k]   (K = 1024)
// Operands PRE-ROUNDED to tf32. cp.async double-buffered smem pipeline.
// MODE 0: qkv projection -> RoPE + head-scatter to g_q/g_k/g_v (tf32-rounded)
// MODE 1: plain fp32 store to Out
// ---------------------------------------------------------------------------
template<int MODE>
__global__ __launch_bounds__(256, 2) void mm_tf32(
    const float* __restrict__ A, const float* __restrict__ Bw,
    float* __restrict__ Out)
{
    __shared__ float As[2][128][20];
    __shared__ float Bs[2][128][20];

    const int tid    = threadIdx.x;
    const int m_base = blockIdx.y * 128;
    const int n_base = blockIdx.x * 128;

    const int ldr = tid >> 2;          // 0..63
    const int ldc = (tid & 3) * 4;     // 0,4,8,12
    const float* Ag = A  + (size_t)(m_base + ldr) * 1024 + ldc;
    const float* Bg = Bw + (size_t)(n_base + ldr) * 1024 + ldc;

    const int warp = tid >> 5;
    const int lane = tid & 31;
    const int wm = warp & 1;
    const int wn = warp >> 1;
    const int g  = lane >> 2;
    const int tg = lane & 3;

    float acc[4][4][4];
#pragma unroll
    for (int mi = 0; mi < 4; mi++)
#pragma unroll
        for (int ni = 0; ni < 4; ni++)
#pragma unroll
            for (int j = 0; j < 4; j++) acc[mi][ni][j] = 0.0f;

    // stage k-tile 0 into buffer 0
    {
        CP16(smem_u32(&As[0][ldr][ldc]),      Ag);
        CP16(smem_u32(&As[0][ldr + 64][ldc]), Ag + (size_t)64 * 1024);
        CP16(smem_u32(&Bs[0][ldr][ldc]),      Bg);
        CP16(smem_u32(&Bs[0][ldr + 64][ldc]), Bg + (size_t)64 * 1024);
        CP_COMMIT;
    }

    for (int kt = 0; kt < 64; ++kt) {
        const int cur = kt & 1;

        if (kt < 63) {
            const int nb = cur ^ 1;
            const float* Ap = Ag + (kt + 1) * 16;
            const float* Bp = Bg + (kt + 1) * 16;
            CP16(smem_u32(&As[nb][ldr][ldc]),      Ap);
            CP16(smem_u32(&As[nb][ldr + 64][ldc]), Ap + (size_t)64 * 1024);
            CP16(smem_u32(&Bs[nb][ldr][ldc]),      Bp);
            CP16(smem_u32(&Bs[nb][ldr + 64][ldc]), Bp + (size_t)64 * 1024);
        }
        CP_COMMIT;           // (empty group on last iter keeps wait-count logic uniform)
        CP_WAIT1;            // newest group may be in flight; tile `kt` is complete
        __syncthreads();

#pragma unroll
        for (int ks = 0; ks < 2; ++ks) {
            const int k0 = ks * 8 + 2 * tg;
            float2 af[4][2], bf[4];
#pragma unroll
            for (int mi = 0; mi < 4; mi++) {
                int r = wm * 64 + mi * 16 + g;
                af[mi][0] = *(const float2*)&As[cur][r][k0];
                af[mi][1] = *(const float2*)&As[cur][r + 8][k0];
            }
#pragma unroll
            for (int ni = 0; ni < 4; ni++) {
                int cN = wn * 32 + ni * 8 + g;
                bf[ni] = *(const float2*)&Bs[cur][cN][k0];
            }
#pragma unroll
            for (int mi = 0; mi < 4; mi++)
#pragma unroll
                for (int ni = 0; ni < 4; ni++)
                    mma_m16n8k8(acc[mi][ni],
                                af[mi][0].x, af[mi][1].x,
                                af[mi][0].y, af[mi][1].y,
                                bf[ni].x, bf[ni].y);
        }
        __syncthreads();     // readers done with `cur` before kt+1's cp.async refills it
    }

#pragma unroll
    for (int mi = 0; mi < 4; mi++) {
        int row0 = m_base + wm * 64 + mi * 16 + g;
#pragma unroll
        for (int ni = 0; ni < 4; ni++) {
            int coln = n_base + wn * 32 + ni * 8 + 2 * tg;
            if (MODE == 0) {
                int part = coln >> 10;
                int cc   = coln & 1023;
                int h    = cc >> 6;
                int d0   = cc & 63;
                int i0   = d0 >> 1;
                float* dst = (part == 0) ? g_q : (part == 1) ? g_k : g_v;
#pragma unroll
                for (int half = 0; half < 2; half++) {
                    int m = row0 + half * 8;
                    int b = m >> 11, s = m & 2047;
                    float v0 = acc[mi][ni][half * 2 + 0];
                    float v1 = acc[mi][ni][half * 2 + 1];
                    if (part < 2) {
                        float cs = g_cos[s * 32 + i0], sn = g_sin[s * 32 + i0];
                        float r0 = v0 * cs - v1 * sn;
                        float r1 = v0 * sn + v1 * cs;
                        v0 = r0; v1 = r1;
                    }
                    *(float2*)(dst + (((size_t)(b * NHEAD + h) * S_LEN + s) * HDIM + d0))
                        = make_float2(to_tf32(v0), to_tf32(v1));
                }
            } else {
#pragma unroll
                for (int half = 0; half < 2; half++) {
                    int m = row0 + half * 8;
                    *(float2*)(Out + (size_t)m * 1024 + coln)
                        = make_float2(acc[mi][ni][half * 2 + 0],
                                      acc[mi][ni][half * 2 + 1]);
                }
            }
        }
    }
}

// ---------------------------------------------------------------------------
// Tensor-core flash attention (tf32 mma.sync).
// CTA: 256 threads = 8 warps; q-tile 128 rows (warp owns 16 rows = 1 m-subtile);
// k-tile 64 keys; cp.async double-buffered K/V/bias; causal per-warp tile skip.
// Smem 109KB -> 2 CTAs/SM.  Fragment k-permutation on both operands of both
// MMAs -> the S accumulator IS the PV A-fragment (P never touches smem).
// ---------------------------------------------------------------------------
#define ATTN_SM_FLOATS (128*72 + 2*64*72 + 2*64*68 + 2*64)
#define ATTN_SM_BYTES  (ATTN_SM_FLOATS * 4)

// Stage one full 64x64 K tile and 64x64 V tile (+64-float bias) via cp.async.
__device__ __forceinline__ void stage_kv(
    float* Kdst, float* Vdst, float* PMdst,
    const float* Kg, const float* Vg, const float* Bsrc, int tid)
{
#pragma unroll
    for (int i = 0; i < 4; ++i) {
        int idx = tid + i * 256;
        int row = idx >> 4;
        int c4  = (idx & 15) * 4;
        CP16(smem_u32(Kdst + row * 72 + c4), Kg + (size_t)row * 64 + c4);
        CP16(smem_u32(Vdst + row * 68 + c4), Vg + (size_t)row * 64 + c4);
    }
    if (tid < 16) CP16(smem_u32(PMdst + tid * 4), Bsrc + tid * 4);
}

__global__ __launch_bounds__(256, 2) void attn_tc()
{
    extern __shared__ float sm[];
    float* Qs = sm;                        // [128][72]
    float* Ks = Qs + 128 * 72;             // [2][64][72]
    float* Vs = Ks + 2 * 64 * 72;          // [2][64][68]
    float* PM = Vs + 2 * 64 * 68;          // [2][64]

    const int qt    = 15 - (int)blockIdx.x;         // heavy tiles first
    const int qbase = qt * 128;
    const int bh = blockIdx.y;
    const int b  = bh >> 4, h = bh & 15;
    const int tid  = threadIdx.x;
    const int warp = tid >> 5, lane = tid & 31;
    const int g = lane >> 2, tg = lane & 3;
    const int nkt = 2 * (qt + 1);

    const float* Kg = g_k + (size_t)bh * S_LEN * HDIM;
    const float* Vg = g_v + (size_t)bh * S_LEN * HDIM;
    const float* Bg = g_bias + b * S_LEN;

    // prefetch k-tile 0
    stage_kv(Ks, Vs, PM, Kg, Vg, Bg, tid);
    CP_COMMIT;

    // stage Q tile [128][64] -> Qs[128][72]
    {
        const float* Qg = g_q + ((size_t)bh * S_LEN + qbase) * HDIM;
#pragma unroll
        for (int r = 0; r < 8; ++r) {
            int idx = tid + r * 256;
            int row = idx >> 4, c4 = (idx & 15) * 4;
            *(float4*)&Qs[row * 72 + c4] = *(const float4*)&Qg[row * 64 + c4];
        }
    }

    float S[8][4], O[8][4], mrow[2], lrow[2];
    mrow[0] = mrow[1] = -INFINITY;
    lrow[0] = lrow[1] = 0.0f;
#pragma unroll
    for (int t = 0; t < 8; t++)
#pragma unroll
        for (int j = 0; j < 4; j++) O[t][j] = 0.0f;

    const int wrow0 = qbase + warp * 16;
    const float scale = 0.125f;   // 1/sqrt(64)

    for (int kt = 0; kt < nkt; ++kt) {
        const int buf   = kt & 1;
        const int kbase = kt * 64;

        if (kt + 1 < nkt) {
            int nb  = (kt + 1) & 1;
            int kb2 = (kt + 1) * 64;
            stage_kv(Ks + nb * 4608, Vs + nb * 4352, PM + nb * 64,
                     Kg + (size_t)kb2 * 64, Vg + (size_t)kb2 * 64, Bg + kb2, tid);
        }
        CP_COMMIT;
        CP_WAIT1;
        __syncthreads();

        if (kbase <= wrow0 + 15) {     // per-warp causal tile skip
            const float* Kb  = Ks + buf * 4608;
            const float* Vb  = Vs + buf * 4352;
            const float* PMb = PM + buf * 64;

            // ---- S = Q K^T
#pragma unroll
            for (int nt = 0; nt < 8; nt++)
#pragma unroll
                for (int j = 0; j < 4; j++) S[nt][j] = 0.0f;

#pragma unroll
            for (int ks = 0; ks < 8; ++ks) {
                int kcol = 8 * ks + 2 * tg;
                float2 a0 = *(const float2*)&Qs[(warp * 16 + g    ) * 72 + kcol];
                float2 a1 = *(const float2*)&Qs[(warp * 16 + g + 8) * 72 + kcol];
#pragma unroll
                for (int nt = 0; nt < 8; ++nt) {
                    float2 bb = *(const float2*)&Kb[(nt * 8 + g) * 72 + kcol];
                    mma_m16n8k8(S[nt], a0.x, a1.x, a0.y, a1.y, bb.x, bb.y);
                }
            }

            // ---- mask + online softmax
            float2 pmb[8];
#pragma unroll
            for (int nt = 0; nt < 8; nt++)
                pmb[nt] = *(const float2*)&PMb[nt * 8 + 2 * tg];

            const bool do_causal = (kbase + 63 > wrow0);

            {
                int row_lo = wrow0 + g;
                int row_hi = row_lo + 8;
                float mx_lo = -INFINITY, mx_hi = -INFINITY;
#pragma unroll
                for (int nt = 0; nt < 8; nt++) {
                    int col0 = kbase + nt * 8 + 2 * tg;
                    float v0 = S[nt][0] * scale + pmb[nt].x;
                    float v1 = S[nt][1] * scale + pmb[nt].y;
                    float v2 = S[nt][2] * scale + pmb[nt].x;
                    float v3 = S[nt][3] * scale + pmb[nt].y;
                    if (do_causal) {
                        if (col0     > row_lo) v0 = -1e30f;
                        if (col0 + 1 > row_lo) v1 = -1e30f;
                        if (col0     > row_hi) v2 = -1e30f;
                        if (col0 + 1 > row_hi) v3 = -1e30f;
                    }
                    S[nt][0] = v0; S[nt][1] = v1;
                    S[nt][2] = v2; S[nt][3] = v3;
                    mx_lo = fmaxf(mx_lo, fmaxf(v0, v1));
                    mx_hi = fmaxf(mx_hi, fmaxf(v2, v3));
                }
                mx_lo = fmaxf(mx_lo, __shfl_xor_sync(0xffffffffu, mx_lo, 1));
                mx_lo = fmaxf(mx_lo, __shfl_xor_sync(0xffffffffu, mx_lo, 2));
                mx_hi = fmaxf(mx_hi, __shfl_xor_sync(0xffffffffu, mx_hi, 1));
                mx_hi = fmaxf(mx_hi, __shfl_xor_sync(0xffffffffu, mx_hi, 2));

                float mn_lo = fmaxf(mrow[0], mx_lo);
                float mn_hi = fmaxf(mrow[1], mx_hi);
                float al_lo = __expf(mrow[0] - mn_lo);
                float al_hi = __expf(mrow[1] - mn_hi);

                float s_lo = 0.0f, s_hi = 0.0f;
#pragma unroll
                for (int nt = 0; nt < 8; nt++) {
                    float p0 = __expf(S[nt][0] - mn_lo);
                    float p1 = __expf(S[nt][1] - mn_lo);
                    float p2 = __expf(S[nt][2] - mn_hi);
                    float p3 = __expf(S[nt][3] - mn_hi);
                    s_lo += p0 + p1;
                    s_hi += p2 + p3;
                    S[nt][0] = to_tf32(p0);
                    S[nt][1] = to_tf32(p1);
                    S[nt][2] = to_tf32(p2);
                    S[nt][3] = to_tf32(p3);
                }
                s_lo += __shfl_xor_sync(0xffffffffu, s_lo, 1);
                s_lo += __shfl_xor_sync(0xffffffffu, s_lo, 2);
                s_hi += __shfl_xor_sync(0xffffffffu, s_hi, 1);
                s_hi += __shfl_xor_sync(0xffffffffu, s_hi, 2);

                lrow[0] = lrow[0] * al_lo + s_lo;
                lrow[1] = lrow[1] * al_hi + s_hi;
                mrow[0] = mn_lo;
                mrow[1] = mn_hi;
#pragma unroll
                for (int hd = 0; hd < 8; hd++) {
                    O[hd][0] *= al_lo;
                    O[hd][1] *= al_lo;
                    O[hd][2] *= al_hi;
                    O[hd][3] *= al_hi;
                }
            }

            // ---- O += P V  (A-fragments = S accumulators, B from Vs)
#pragma unroll
            for (int ks = 0; ks < 8; ++ks) {
#pragma unroll
                for (int hd = 0; hd < 8; ++hd) {
                    float b0 = Vb[(ks * 8 + 2 * tg    ) * 68 + hd * 8 + g];
                    float b1 = Vb[(ks * 8 + 2 * tg + 1) * 68 + hd * 8 + g];
                    mma_m16n8k8(O[hd], S[ks][0], S[ks][2],
                                       S[ks][1], S[ks][3], b0, b1);
                }
            }
        }
        __syncthreads();
    }

    // epilogue: normalize + write g_attn (tf32-rounded for the out-proj GEMM)
    {
        float inv_lo = 1.0f / lrow[0];
        float inv_hi = 1.0f / lrow[1];
        int row_lo = wrow0 + g;
#pragma unroll
        for (int hd = 0; hd < 8; hd++) {
            int col = h * 64 + hd * 8 + 2 * tg;
            *(float2*)(g_attn + ((size_t)b * S_LEN + row_lo) * D_MODEL + col) =
                make_float2(to_tf32(O[hd][0] * inv_lo),
                            to_tf32(O[hd][1] * inv_lo));
            *(float2*)(g_attn + ((size_t)b * S_LEN + row_lo + 8) * D_MODEL + col) =
                make_float2(to_tf32(O[hd][2] * inv_hi),
                            to_tf32(O[hd][3] * inv_hi));
        }
    }
}

// ---------------------------------------------------------------------------
extern "C" void kernel_launch(void* const* d_in, const int* in_sizes, int n_in,
                              void* d_out, int out_size)
{
    const float* x      = (const float*)d_in[0];
    const int*   pmask  = (const int*)d_in[1];
    const float* w_qkv  = (const float*)d_in[2];
    const float* w_o    = (const float*)d_in[3];
    float*       out    = (float*)d_out;

    cudaFuncSetAttribute(attn_tc,
                         cudaFuncAttributeMaxDynamicSharedMemorySize,
                         ATTN_SM_BYTES);

    float *xc, *wc, *woc, *attn_ptr;
    cudaGetSymbolAddress((void**)&xc, g_xc);
    cudaGetSymbolAddress((void**)&wc, g_wc);
    cudaGetSymbolAddress((void**)&woc, g_woc);
    cudaGetSymbolAddress((void**)&attn_ptr, g_attn);

    rope_table_kernel<<<(S_LEN * 32 + 255) / 256, 256>>>();
    // preconvert operands to tf32 (no cvt in GEMM hot loops)
    cvt_tf32_kernel<<<(2097152 + 255) / 256, 256>>>((const float4*)x, (float4*)xc, 2097152);
    cvt_tf32_kernel<<<(786432 + 255) / 256, 256>>>((const float4*)w_qkv, (float4*)wc, 786432);
    cvt_tf32_kernel<<<(262144 + 255) / 256, 256>>>((const float4*)w_o, (float4*)woc, 262144);
    bias_kernel<<<(BATCH * S_LEN + 255) / 256, 256>>>(pmask);

    // QKV projection + RoPE: M=8192, N=3072
    mm_tf32<0><<<dim3(3 * D_MODEL / 128, (BATCH * S_LEN) / 128), 256>>>(xc, wc, nullptr);
    // Flash attention (tensor cores), q-tile 128 rows
    attn_tc<<<dim3(16, BH), 256, ATTN_SM_BYTES>>>();
    // Output projection: M=8192, N=1024
    mm_tf32<1><<<dim3(D_MODEL / 128, (BATCH * S_LEN) / 128), 256>>>(attn_ptr, woc, out);
}

// round 6
// speedup vs baseline: 3.1086x; 1.0299x over previous
#include <cuda_runtime.h>
#include <math.h>
#include <stdint.h>

// Problem constants
#define S_LEN   2048
#define D_MODEL 1024
#define NHEAD   16
#define HDIM    64
#define BATCH   4
#define BH      (BATCH * NHEAD)   // 64

// Scratch (device globals — no allocation allowed)
__device__ float g_q[(size_t)BH * S_LEN * HDIM];          // [B,H,S,hd] rope'd, pre-scaled, tf32
__device__ float g_k[(size_t)BH * S_LEN * HDIM];
__device__ float g_v[(size_t)BH * S_LEN * HDIM];
__device__ float g_attn[(size_t)BATCH * S_LEN * D_MODEL]; // [B,S,D], tf32-rounded
__device__ float g_cos[S_LEN * (HDIM / 2)];
__device__ float g_sin[S_LEN * (HDIM / 2)];
__device__ float g_xc[(size_t)BATCH * S_LEN * D_MODEL];   // tf32-rounded x
__device__ float g_wc[(size_t)3 * D_MODEL * D_MODEL];     // tf32-rounded w_qkv
__device__ float g_woc[(size_t)D_MODEL * D_MODEL];        // tf32-rounded w_o
__device__ float g_bias[BATCH * S_LEN];                   // 0 or -1e30 padding bias

// ---------------------------------------------------------------------------
// helpers
// ---------------------------------------------------------------------------
__device__ __forceinline__ float to_tf32(float x) {
    float r;
    asm("cvt.rna.tf32.f32 %0, %1;" : "=f"(r) : "f"(x));
    return r;
}

__device__ __forceinline__ void mma_m16n8k8(
    float* c, float a0, float a1, float a2, float a3, float b0, float b1)
{
    uint32_t ua0 = __float_as_uint(a0), ua1 = __float_as_uint(a1);
    uint32_t ua2 = __float_as_uint(a2), ua3 = __float_as_uint(a3);
    uint32_t ub0 = __float_as_uint(b0), ub1 = __float_as_uint(b1);
    asm volatile(
        "mma.sync.aligned.m16n8k8.row.col.f32.tf32.tf32.f32 "
        "{%0,%1,%2,%3}, {%4,%5,%6,%7}, {%8,%9}, {%0,%1,%2,%3};"
        : "+f"(c[0]), "+f"(c[1]), "+f"(c[2]), "+f"(c[3])
        : "r"(ua0), "r"(ua1), "r"(ua2), "r"(ua3), "r"(ub0), "r"(ub1));
}

__device__ __forceinline__ uint32_t smem_u32(const void* p) {
    return (uint32_t)__cvta_generic_to_shared(p);
}
#define CP16(d, s)  asm volatile("cp.async.ca.shared.global [%0], [%1], 16;" :: "r"(d), "l"(s))
#define CP_COMMIT   asm volatile("cp.async.commit_group;")
#define CP_WAIT0    asm volatile("cp.async.wait_group 0;")
#define CP_WAIT1    asm volatile("cp.async.wait_group 1;")

// ---------------------------------------------------------------------------
// prep kernels
// ---------------------------------------------------------------------------
__global__ void rope_table_kernel() {
    int idx = blockIdx.x * blockDim.x + threadIdx.x;
    if (idx >= S_LEN * (HDIM / 2)) return;
    int s = idx >> 5;
    int i = idx & 31;
    float inv = exp2f(-13.287712379549449f * (2.0f * (float)i / 64.0f));
    float ang = (float)s * inv;
    float sn, cs;
    sincosf(ang, &sn, &cs);
    g_cos[idx] = cs;
    g_sin[idx] = sn;
}

// Fused tf32 conversion of x (2097152 f4), w_qkv (786432 f4), w_o (262144 f4).
#define N4_X  2097152
#define N4_W  786432
#define N4_WO 262144
__global__ void cvt_all_kernel(const float4* __restrict__ x,
                               const float4* __restrict__ w,
                               const float4* __restrict__ wo) {
    int i = blockIdx.x * blockDim.x + threadIdx.x;
    const float4* src;
    float4* dst;
    if (i < N4_X)                    { src = x + i;                 dst = (float4*)g_xc + i; }
    else if (i < N4_X + N4_W)        { src = w + (i - N4_X);        dst = (float4*)g_wc + (i - N4_X); }
    else if (i < N4_X + N4_W + N4_WO){ src = wo + (i - N4_X - N4_W);dst = (float4*)g_woc + (i - N4_X - N4_W); }
    else return;
    float4 v = *src;
    *dst = make_float4(to_tf32(v.x), to_tf32(v.y), to_tf32(v.z), to_tf32(v.w));
}

__global__ void bias_kernel(const int* __restrict__ pmask) {
    int i = blockIdx.x * blockDim.x + threadIdx.x;
    if (i < BATCH * S_LEN)
        g_bias[i] = (pmask[i] == 0) ? -1e30f : 0.0f;
}

// ---------------------------------------------------------------------------
// tf32 tensor-core GEMM: C[m,n] = sum_k A[m,k] * Bw[n,k]   (K = 1024)
// 3-stage cp.async ring, ONE __syncthreads per BK=16 tile.
// MODE 0: qkv projection -> RoPE + 0.125 q-scale + head-scatter (tf32-rounded)
// MODE 1: plain fp32 store to Out
// ---------------------------------------------------------------------------
#define MM_STAGE_FLOATS (128 * 20)
#define MM_SM_BYTES     (6 * MM_STAGE_FLOATS * 4)   // 3 stages x (A + B) = 61440B

template<int MODE>
__global__ __launch_bounds__(256, 2) void mm_tf32(
    const float* __restrict__ A, const float* __restrict__ Bw,
    float* __restrict__ Out)
{
    extern __shared__ float smbuf[];
    // stage s: A at smbuf + s*2560, B at smbuf + 7680 + s*2560 ; row stride 20

    const int tid    = threadIdx.x;
    const int m_base = blockIdx.y * 128;
    const int n_base = blockIdx.x * 128;

    const int ldr = tid >> 2;          // 0..63
    const int ldc = (tid & 3) * 4;     // 0,4,8,12
    const float* Ag = A  + (size_t)(m_base + ldr) * 1024 + ldc;
    const float* Bg = Bw + (size_t)(n_base + ldr) * 1024 + ldc;

    const int warp = tid >> 5;
    const int lane = tid & 31;
    const int wm = warp & 1;
    const int wn = warp >> 1;
    const int g  = lane >> 2;
    const int tg = lane & 3;

    float acc[4][4][4];
#pragma unroll
    for (int mi = 0; mi < 4; mi++)
#pragma unroll
        for (int ni = 0; ni < 4; ni++)
#pragma unroll
            for (int j = 0; j < 4; j++) acc[mi][ni][j] = 0.0f;

    // prologue: stage tiles 0 and 1 (groups G0, G1)
#pragma unroll
    for (int p = 0; p < 2; ++p) {
        float* Asb = smbuf + p * MM_STAGE_FLOATS;
        float* Bsb = smbuf + 3 * MM_STAGE_FLOATS + p * MM_STAGE_FLOATS;
        const float* Ap = Ag + p * 16;
        const float* Bp = Bg + p * 16;
        CP16(smem_u32(Asb + ldr * 20 + ldc),        Ap);
        CP16(smem_u32(Asb + (ldr + 64) * 20 + ldc), Ap + (size_t)64 * 1024);
        CP16(smem_u32(Bsb + ldr * 20 + ldc),        Bp);
        CP16(smem_u32(Bsb + (ldr + 64) * 20 + ldc), Bp + (size_t)64 * 1024);
        CP_COMMIT;
    }

    int sidx = 0;   // stage of tile kt (ring of 3)
    for (int kt = 0; kt < 64; ++kt) {
        CP_WAIT1;          // pending {G(kt),G(kt+1)} -> completes G(kt): tile kt ready
        __syncthreads();   // visibility + readers of tile kt-1 done (buf reuse guard)

        {   // prefetch tile kt+2 into stage (sidx+2)%3  ( == stage of tile kt-1 )
            int ps = sidx + 2; if (ps >= 3) ps -= 3;
            if (kt + 2 < 64) {
                float* Asb = smbuf + ps * MM_STAGE_FLOATS;
                float* Bsb = smbuf + 3 * MM_STAGE_FLOATS + ps * MM_STAGE_FLOATS;
                const float* Ap = Ag + (kt + 2) * 16;
                const float* Bp = Bg + (kt + 2) * 16;
                CP16(smem_u32(Asb + ldr * 20 + ldc),        Ap);
                CP16(smem_u32(Asb + (ldr + 64) * 20 + ldc), Ap + (size_t)64 * 1024);
                CP16(smem_u32(Bsb + ldr * 20 + ldc),        Bp);
                CP16(smem_u32(Bsb + (ldr + 64) * 20 + ldc), Bp + (size_t)64 * 1024);
            }
            CP_COMMIT;     // commit even when empty: keeps group-count invariant
        }

        const float* Asb = smbuf + sidx * MM_STAGE_FLOATS;
        const float* Bsb = smbuf + 3 * MM_STAGE_FLOATS + sidx * MM_STAGE_FLOATS;
#pragma unroll
        for (int ks = 0; ks < 2; ++ks) {
            const int k0 = ks * 8 + 2 * tg;
            float2 af[4][2], bf[4];
#pragma unroll
            for (int mi = 0; mi < 4; mi++) {
                int r = wm * 64 + mi * 16 + g;
                af[mi][0] = *(const float2*)&Asb[r * 20 + k0];
                af[mi][1] = *(const float2*)&Asb[(r + 8) * 20 + k0];
            }
#pragma unroll
            for (int ni = 0; ni < 4; ni++) {
                int cN = wn * 32 + ni * 8 + g;
                bf[ni] = *(const float2*)&Bsb[cN * 20 + k0];
            }
#pragma unroll
            for (int mi = 0; mi < 4; mi++)
#pragma unroll
                for (int ni = 0; ni < 4; ni++)
                    mma_m16n8k8(acc[mi][ni],
                                af[mi][0].x, af[mi][1].x,
                                af[mi][0].y, af[mi][1].y,
                                bf[ni].x, bf[ni].y);
        }
        if (++sidx == 3) sidx = 0;
    }

#pragma unroll
    for (int mi = 0; mi < 4; mi++) {
        int row0 = m_base + wm * 64 + mi * 16 + g;
#pragma unroll
        for (int ni = 0; ni < 4; ni++) {
            int coln = n_base + wn * 32 + ni * 8 + 2 * tg;
            if (MODE == 0) {
                int part = coln >> 10;
                int cc   = coln & 1023;
                int h    = cc >> 6;
                int d0   = cc & 63;
                int i0   = d0 >> 1;
                float* dst = (part == 0) ? g_q : (part == 1) ? g_k : g_v;
                float qsc = (part == 0) ? 0.125f : 1.0f;   // fold softmax scale into q
#pragma unroll
                for (int half = 0; half < 2; half++) {
                    int m = row0 + half * 8;
                    int b = m >> 11, s = m & 2047;
                    float v0 = acc[mi][ni][half * 2 + 0];
                    float v1 = acc[mi][ni][half * 2 + 1];
                    if (part < 2) {
                        float cs = g_cos[s * 32 + i0], sn = g_sin[s * 32 + i0];
                        float r0 = v0 * cs - v1 * sn;
                        float r1 = v0 * sn + v1 * cs;
                        v0 = r0 * qsc; v1 = r1 * qsc;
                    }
                    *(float2*)(dst + (((size_t)(b * NHEAD + h) * S_LEN + s) * HDIM + d0))
                        = make_float2(to_tf32(v0), to_tf32(v1));
                }
            } else {
#pragma unroll
                for (int half = 0; half < 2; half++) {
                    int m = row0 + half * 8;
                    *(float2*)(Out + (size_t)m * 1024 + coln)
                        = make_float2(acc[mi][ni][half * 2 + 0],
                                      acc[mi][ni][half * 2 + 1]);
                }
            }
        }
    }
}

// ---------------------------------------------------------------------------
// Tensor-core flash attention (tf32 mma.sync).
// q-tile 128 rows, k-tile 64 keys, 2-stage cp.async, ONE barrier per k-tile.
// Q pre-scaled by 1/8 at the QKV epilogue (no scale multiply here).
// ---------------------------------------------------------------------------
#define ATTN_SM_FLOATS (128*72 + 2*64*72 + 2*64*68 + 2*64)
#define ATTN_SM_BYTES  (ATTN_SM_FLOATS * 4)

__device__ __forceinline__ void stage_kv(
    float* Kdst, float* Vdst, float* PMdst,
    const float* Kg, const float* Vg, const float* Bsrc, int tid)
{
#pragma unroll
    for (int i = 0; i < 4; ++i) {
        int idx = tid + i * 256;
        int row = idx >> 4;
        int c4  = (idx & 15) * 4;
        CP16(smem_u32(Kdst + row * 72 + c4), Kg + (size_t)row * 64 + c4);
        CP16(smem_u32(Vdst + row * 68 + c4), Vg + (size_t)row * 64 + c4);
    }
    if (tid < 16) CP16(smem_u32(PMdst + tid * 4), Bsrc + tid * 4);
}

__global__ __launch_bounds__(256, 2) void attn_tc()
{
    extern __shared__ float sm[];
    float* Qs = sm;                        // [128][72]
    float* Ks = Qs + 128 * 72;             // [2][64][72]
    float* Vs = Ks + 2 * 64 * 72;          // [2][64][68]
    float* PM = Vs + 2 * 64 * 68;          // [2][64]

    const int qt    = 15 - (int)blockIdx.x;         // heavy tiles first
    const int qbase = qt * 128;
    const int bh = blockIdx.y;
    const int b  = bh >> 4, h = bh & 15;
    const int tid  = threadIdx.x;
    const int warp = tid >> 5, lane = tid & 31;
    const int g = lane >> 2, tg = lane & 3;
    const int nkt = 2 * (qt + 1);

    const float* Kg = g_k + (size_t)bh * S_LEN * HDIM;
    const float* Vg = g_v + (size_t)bh * S_LEN * HDIM;
    const float* Bg = g_bias + b * S_LEN;

    // prefetch k-tile 0
    stage_kv(Ks, Vs, PM, Kg, Vg, Bg, tid);
    CP_COMMIT;

    // stage Q tile [128][64] -> Qs[128][72]
    {
        const float* Qg = g_q + ((size_t)bh * S_LEN + qbase) * HDIM;
#pragma unroll
        for (int r = 0; r < 8; ++r) {
            int idx = tid + r * 256;
            int row = idx >> 4, c4 = (idx & 15) * 4;
            *(float4*)&Qs[row * 72 + c4] = *(const float4*)&Qg[row * 64 + c4];
        }
    }

    float S[8][4], O[8][4], mrow[2], lrow[2];
    mrow[0] = mrow[1] = -INFINITY;
    lrow[0] = lrow[1] = 0.0f;
#pragma unroll
    for (int t = 0; t < 8; t++)
#pragma unroll
        for (int j = 0; j < 4; j++) O[t][j] = 0.0f;

    const int wrow0 = qbase + warp * 16;

    for (int kt = 0; kt < nkt; ++kt) {
        const int buf   = kt & 1;
        const int kbase = kt * 64;

        CP_WAIT0;           // tile kt complete (only pending group)
        __syncthreads();    // visibility + all warps done with tile kt-1 (buf reuse)

        if (kt + 1 < nkt) { // prefetch kt+1 into the buffer tile kt-1 used
            int nb  = buf ^ 1;
            int kb2 = (kt + 1) * 64;
            stage_kv(Ks + nb * 4608, Vs + nb * 4352, PM + nb * 64,
                     Kg + (size_t)kb2 * 64, Vg + (size_t)kb2 * 64, Bg + kb2, tid);
        }
        CP_COMMIT;

        if (kbase <= wrow0 + 15) {     // per-warp causal tile skip
            const float* Kb  = Ks + buf * 4608;
            const float* Vb  = Vs + buf * 4352;
            const float* PMb = PM + buf * 64;

            // ---- S = Q K^T (q pre-scaled by 1/8)
#pragma unroll
            for (int nt = 0; nt < 8; nt++)
#pragma unroll
                for (int j = 0; j < 4; j++) S[nt][j] = 0.0f;

#pragma unroll
            for (int ks = 0; ks < 8; ++ks) {
                int kcol = 8 * ks + 2 * tg;
                float2 a0 = *(const float2*)&Qs[(warp * 16 + g    ) * 72 + kcol];
                float2 a1 = *(const float2*)&Qs[(warp * 16 + g + 8) * 72 + kcol];
#pragma unroll
                for (int nt = 0; nt < 8; ++nt) {
                    float2 bb = *(const float2*)&Kb[(nt * 8 + g) * 72 + kcol];
                    mma_m16n8k8(S[nt], a0.x, a1.x, a0.y, a1.y, bb.x, bb.y);
                }
            }

            // ---- mask + online softmax
            float2 pmb[8];
#pragma unroll
            for (int nt = 0; nt < 8; nt++)
                pmb[nt] = *(const float2*)&PMb[nt * 8 + 2 * tg];

            const bool do_causal = (kbase + 63 > wrow0);

            {
                int row_lo = wrow0 + g;
                int row_hi = row_lo + 8;
                float mx_lo = -INFINITY, mx_hi = -INFINITY;
#pragma unroll
                for (int nt = 0; nt < 8; nt++) {
                    int col0 = kbase + nt * 8 + 2 * tg;
                    float v0 = S[nt][0] + pmb[nt].x;
                    float v1 = S[nt][1] + pmb[nt].y;
                    float v2 = S[nt][2] + pmb[nt].x;
                    float v3 = S[nt][3] + pmb[nt].y;
                    if (do_causal) {
                        if (col0     > row_lo) v0 = -1e30f;
                        if (col0 + 1 > row_lo) v1 = -1e30f;
                        if (col0     > row_hi) v2 = -1e30f;
                        if (col0 + 1 > row_hi) v3 = -1e30f;
                    }
                    S[nt][0] = v0; S[nt][1] = v1;
                    S[nt][2] = v2; S[nt][3] = v3;
                    mx_lo = fmaxf(mx_lo, fmaxf(v0, v1));
                    mx_hi = fmaxf(mx_hi, fmaxf(v2, v3));
                }
                mx_lo = fmaxf(mx_lo, __shfl_xor_sync(0xffffffffu, mx_lo, 1));
                mx_lo = fmaxf(mx_lo, __shfl_xor_sync(0xffffffffu, mx_lo, 2));
                mx_hi = fmaxf(mx_hi, __shfl_xor_sync(0xffffffffu, mx_hi, 1));
                mx_hi = fmaxf(mx_hi, __shfl_xor_sync(0xffffffffu, mx_hi, 2));

                float mn_lo = fmaxf(mrow[0], mx_lo);
                float mn_hi = fmaxf(mrow[1], mx_hi);
                float al_lo = __expf(mrow[0] - mn_lo);
                float al_hi = __expf(mrow[1] - mn_hi);

                float s_lo = 0.0f, s_hi = 0.0f;
#pragma unroll
                for (int nt = 0; nt < 8; nt++) {
                    float p0 = __expf(S[nt][0] - mn_lo);
                    float p1 = __expf(S[nt][1] - mn_lo);
                    float p2 = __expf(S[nt][2] - mn_hi);
                    float p3 = __expf(S[nt][3] - mn_hi);
                    s_lo += p0 + p1;
                    s_hi += p2 + p3;
                    S[nt][0] = to_tf32(p0);
                    S[nt][1] = to_tf32(p1);
                    S[nt][2] = to_tf32(p2);
                    S[nt][3] = to_tf32(p3);
                }
                s_lo += __shfl_xor_sync(0xffffffffu, s_lo, 1);
                s_lo += __shfl_xor_sync(0xffffffffu, s_lo, 2);
                s_hi += __shfl_xor_sync(0xffffffffu, s_hi, 1);
                s_hi += __shfl_xor_sync(0xffffffffu, s_hi, 2);

                lrow[0] = lrow[0] * al_lo + s_lo;
                lrow[1] = lrow[1] * al_hi + s_hi;
                mrow[0] = mn_lo;
                mrow[1] = mn_hi;
#pragma unroll
                for (int hd = 0; hd < 8; hd++) {
                    O[hd][0] *= al_lo;
                    O[hd][1] *= al_lo;
                    O[hd][2] *= al_hi;
                    O[hd][3] *= al_hi;
                }
            }

            // ---- O += P V
#pragma unroll
            for (int ks = 0; ks < 8; ++ks) {
#pragma unroll
                for (int hd = 0; hd < 8; ++hd) {
                    float b0 = Vb[(ks * 8 + 2 * tg    ) * 68 + hd * 8 + g];
                    float b1 = Vb[(ks * 8 + 2 * tg + 1) * 68 + hd * 8 + g];
                    mma_m16n8k8(O[hd], S[ks][0], S[ks][2],
                                       S[ks][1], S[ks][3], b0, b1);
                }
            }
        }
    }

    // epilogue: normalize + write g_attn (tf32-rounded for the out-proj GEMM)
    {
        float inv_lo = 1.0f / lrow[0];
        float inv_hi = 1.0f / lrow[1];
        int row_lo = wrow0 + g;
#pragma unroll
        for (int hd = 0; hd < 8; hd++) {
            int col = h * 64 + hd * 8 + 2 * tg;
            *(float2*)(g_attn + ((size_t)b * S_LEN + row_lo) * D_MODEL + col) =
                make_float2(to_tf32(O[hd][0] * inv_lo),
                            to_tf32(O[hd][1] * inv_lo));
            *(float2*)(g_attn + ((size_t)b * S_LEN + row_lo + 8) * D_MODEL + col) =
                make_float2(to_tf32(O[hd][2] * inv_hi),
                            to_tf32(O[hd][3] * inv_hi));
        }
    }
}

// ---------------------------------------------------------------------------
extern "C" void kernel_launch(void* const* d_in, const int* in_sizes, int n_in,
                              void* d_out, int out_size)
{
    const float* x      = (const float*)d_in[0];
    const int*   pmask  = (const int*)d_in[1];
    const float* w_qkv  = (const float*)d_in[2];
    const float* w_o    = (const float*)d_in[3];
    float*       out    = (float*)d_out;

    cudaFuncSetAttribute(attn_tc,
                         cudaFuncAttributeMaxDynamicSharedMemorySize, ATTN_SM_BYTES);
    cudaFuncSetAttribute(mm_tf32<0>,
                         cudaFuncAttributeMaxDynamicSharedMemorySize, MM_SM_BYTES);
    cudaFuncSetAttribute(mm_tf32<1>,
                         cudaFuncAttributeMaxDynamicSharedMemorySize, MM_SM_BYTES);

    float *xc, *wc, *woc, *attn_ptr;
    cudaGetSymbolAddress((void**)&xc, g_xc);
    cudaGetSymbolAddress((void**)&wc, g_wc);
    cudaGetSymbolAddress((void**)&woc, g_woc);
    cudaGetSymbolAddress((void**)&attn_ptr, g_attn);

    rope_table_kernel<<<(S_LEN * 32 + 255) / 256, 256>>>();
    cvt_all_kernel<<<(N4_X + N4_W + N4_WO + 255) / 256, 256>>>(
        (const float4*)x, (const float4*)w_qkv, (const float4*)w_o);
    bias_kernel<<<(BATCH * S_LEN + 255) / 256, 256>>>(pmask);

    // QKV projection + RoPE (+1/8 q-scale): M=8192, N=3072
    mm_tf32<0><<<dim3(3 * D_MODEL / 128, (BATCH * S_LEN) / 128), 256, MM_SM_BYTES>>>(xc, wc, nullptr);
    // Flash attention (tensor cores), q-tile 128 rows
    attn_tc<<<dim3(16, BH), 256, ATTN_SM_BYTES>>>();
    // Output projection: M=8192, N=1024
    mm_tf32<1><<<dim3(D_MODEL / 128, (BATCH * S_LEN) / 128), 256, MM_SM_BYTES>>>(attn_ptr, woc, out);
}